// round 3
// baseline (speedup 1.0000x reference)
#include <cuda_runtime.h>
#include <cstdint>
#include <cstddef>

#define N_NODES 20000
#define N_EDGES 320000
#define N_ETOT  340000   // edges + self loops

// ---------------- scratch (static device arrays; no allocation) ----------------
__device__ float g_h0[N_NODES*64];
__device__ float g_h1[N_NODES*256];
__device__ float g_h2[N_NODES*64];
__device__ float g_xw[N_NODES*256];
__device__ float g_attS[N_NODES*4];
__device__ float g_attD[N_NODES*4];
__device__ float g_dis[N_NODES];
__device__ int   g_counts[N_NODES];
__device__ int   g_offs[N_NODES+1];
__device__ int   g_cursor[N_NODES];
__device__ int   g_ssrc[N_ETOT];
__device__ int   g_seid[N_ETOT];

// ---------------- CSR build ----------------
__global__ void k_init_counts() {
    int i = blockIdx.x*blockDim.x + threadIdx.x;
    if (i < N_NODES) g_counts[i] = 1;   // self loop
}

__global__ void k_count(const int* __restrict__ dst) {
    int e = blockIdx.x*blockDim.x + threadIdx.x;
    if (e < N_EDGES) atomicAdd(&g_counts[dst[e]], 1);
}

// single-block exclusive scan over 20000 ints (Hillis-Steele per 1024 chunk)
__global__ void k_scan() {
    __shared__ int sh[1024];
    __shared__ int carry;
    int tid = threadIdx.x;
    if (tid == 0) carry = 0;
    __syncthreads();
    for (int base = 0; base < N_NODES; base += 1024) {
        int i = base + tid;
        int v = (i < N_NODES) ? g_counts[i] : 0;
        sh[tid] = v;
        __syncthreads();
        for (int off = 1; off < 1024; off <<= 1) {
            int t = (tid >= off) ? sh[tid-off] : 0;
            __syncthreads();
            sh[tid] += t;
            __syncthreads();
        }
        if (i < N_NODES) g_offs[i] = carry + sh[tid] - v;  // exclusive
        __syncthreads();
        if (tid == 1023) carry += sh[1023];
        __syncthreads();
    }
    if (tid == 0) g_offs[N_NODES] = carry;
}

__global__ void k_finalize() {
    int i = blockIdx.x*blockDim.x + threadIdx.x;
    if (i < N_NODES) {
        g_cursor[i] = g_offs[i];
        int deg = g_offs[i+1] - g_offs[i];          // in-degree incl self loop, >= 1
        g_dis[i] = rsqrtf((float)deg);
    }
}

__global__ void k_scatter(const int* __restrict__ src, const int* __restrict__ dst) {
    int t = blockIdx.x*blockDim.x + threadIdx.x;
    if (t >= N_ETOT) return;
    int s, d;
    if (t < N_EDGES) { s = src[t]; d = dst[t]; }
    else             { s = t - N_EDGES; d = s; }
    int pos = atomicAdd(&g_cursor[d], 1);
    g_ssrc[pos] = s;
    g_seid[pos] = t;  // original edge id (self loops are E..E+N-1, matching reference concat)
}

// ---------------- GEMM: C[M,N] = A[M,K] @ B[K,N]; N%64==0, K%16==0 ----------------
__global__ void gemm64(const float* __restrict__ A, const float* __restrict__ B,
                       float* __restrict__ C, int M, int N, int K) {
    __shared__ float As[16][68];   // [k][m], padded
    __shared__ float Bs[16][64];   // [k][n]
    int tx = threadIdx.x & 15, ty = threadIdx.x >> 4;
    int row0 = blockIdx.y * 64, col0 = blockIdx.x * 64;

    int am  = threadIdx.x >> 2;          // 0..63
    int akq = (threadIdx.x & 3) * 4;     // 0,4,8,12
    int bk  = threadIdx.x >> 4;          // 0..15
    int bn  = (threadIdx.x & 15) * 4;    // 0..60

    float acc[4][4];
#pragma unroll
    for (int i = 0; i < 4; i++)
#pragma unroll
        for (int j = 0; j < 4; j++) acc[i][j] = 0.f;

    for (int k0 = 0; k0 < K; k0 += 16) {
        float4 av = make_float4(0.f, 0.f, 0.f, 0.f);
        int arow = row0 + am;
        if (arow < M) av = *(const float4*)(A + (size_t)arow*K + k0 + akq);
        As[akq+0][am] = av.x; As[akq+1][am] = av.y;
        As[akq+2][am] = av.z; As[akq+3][am] = av.w;
        float4 bv = *(const float4*)(B + (size_t)(k0+bk)*N + col0 + bn);
        *(float4*)&Bs[bk][bn] = bv;
        __syncthreads();
#pragma unroll
        for (int kk = 0; kk < 16; kk++) {
            float4 a = *(float4*)&As[kk][ty*4];
            float4 b = *(float4*)&Bs[kk][tx*4];
            float ar[4] = {a.x, a.y, a.z, a.w};
            float br[4] = {b.x, b.y, b.z, b.w};
#pragma unroll
            for (int i = 0; i < 4; i++)
#pragma unroll
                for (int j = 0; j < 4; j++)
                    acc[i][j] = fmaf(ar[i], br[j], acc[i][j]);
        }
        __syncthreads();
    }
#pragma unroll
    for (int i = 0; i < 4; i++) {
        int r = row0 + ty*4 + i;
        if (r < M) {
            float4 v = make_float4(acc[i][0], acc[i][1], acc[i][2], acc[i][3]);
            *(float4*)(C + (size_t)r*N + col0 + tx*4) = v;
        }
    }
}

// ---------------- GCN aggregate: warp per destination, 64 channels ----------------
__global__ void k_gcn_agg(const float* __restrict__ bias) {
    int gw = (blockIdx.x*blockDim.x + threadIdx.x) >> 5;
    int lane = threadIdx.x & 31;
    if (gw >= N_NODES) return;
    int beg = g_offs[gw], end = g_offs[gw+1];
    float di = g_dis[gw];
    float a0 = 0.f, a1 = 0.f;
    for (int e = beg; e < end; e++) {
        int s = g_ssrc[e];
        float w = g_dis[s] * di;
        const float* row = g_xw + (size_t)s*64;
        a0 = fmaf(w, row[lane],      a0);
        a1 = fmaf(w, row[lane + 32], a1);
    }
    g_h0[(size_t)gw*64 + lane]      = fmaxf(a0 + bias[lane], 0.f);
    g_h0[(size_t)gw*64 + lane + 32] = fmaxf(a1 + bias[lane+32], 0.f);
}

// ---------------- per-node attention terms: als/ald [N,4] ----------------
__global__ void k_att(const float* __restrict__ asrc, const float* __restrict__ adst) {
    int gw = (blockIdx.x*blockDim.x + threadIdx.x) >> 5;
    int lane = threadIdx.x & 31;
    if (gw >= N_NODES) return;
    const float* row = g_xw + (size_t)gw*256;
    float s[4] = {0.f,0.f,0.f,0.f}, d[4] = {0.f,0.f,0.f,0.f};
#pragma unroll
    for (int k = 0; k < 8; k++) {
        int ch = lane + 32*k;
        int h = k >> 1;            // lane-independent head per slot
        int c = ch & 63;
        float v = row[ch];
        s[h] = fmaf(v, __ldg(&asrc[h*64 + c]), s[h]);
        d[h] = fmaf(v, __ldg(&adst[h*64 + c]), d[h]);
    }
#pragma unroll
    for (int off = 16; off; off >>= 1) {
#pragma unroll
        for (int h = 0; h < 4; h++) {
            s[h] += __shfl_xor_sync(0xffffffffu, s[h], off);
            d[h] += __shfl_xor_sync(0xffffffffu, d[h], off);
        }
    }
    if (lane == 0) {
        ((float4*)g_attS)[gw] = make_float4(s[0], s[1], s[2], s[3]);
        ((float4*)g_attD)[gw] = make_float4(d[0], d[1], d[2], d[3]);
    }
}

__device__ __forceinline__ float lrelu(float x) {
    return fmaxf(x, 0.f) + 0.2f * fminf(x, 0.f);
}

// ---------------- GAT aggregate: warp per destination ----------------
// MODE 0: concat (256 out) + bias + relu   (gat1)
// MODE 1: head-mean (64 out) + bias + relu (gat2)
// MODE 2: head-mean (64 out) + bias        (mean/std)
template<int MODE>
__global__ void k_gat_agg(const float* __restrict__ bias,
                          float* __restrict__ alpha_out,
                          float* __restrict__ out) {
    int gw = (blockIdx.x*blockDim.x + threadIdx.x) >> 5;
    int lane = threadIdx.x & 31;
    if (gw >= N_NODES) return;
    int beg = g_offs[gw], end = g_offs[gw+1];
    float4 ad = ((const float4*)g_attD)[gw];

    // pass 1: per-head max over this node's incoming edges
    float m0 = -3.4e38f, m1 = -3.4e38f, m2 = -3.4e38f, m3 = -3.4e38f;
    for (int e = beg + lane; e < end; e += 32) {
        float4 as = ((const float4*)g_attS)[g_ssrc[e]];
        m0 = fmaxf(m0, lrelu(as.x + ad.x));
        m1 = fmaxf(m1, lrelu(as.y + ad.y));
        m2 = fmaxf(m2, lrelu(as.z + ad.z));
        m3 = fmaxf(m3, lrelu(as.w + ad.w));
    }
#pragma unroll
    for (int off = 16; off; off >>= 1) {
        m0 = fmaxf(m0, __shfl_xor_sync(0xffffffffu, m0, off));
        m1 = fmaxf(m1, __shfl_xor_sync(0xffffffffu, m1, off));
        m2 = fmaxf(m2, __shfl_xor_sync(0xffffffffu, m2, off));
        m3 = fmaxf(m3, __shfl_xor_sync(0xffffffffu, m3, off));
    }

    // pass 2: per-head sum of exp
    float t0 = 0.f, t1 = 0.f, t2 = 0.f, t3 = 0.f;
    for (int e = beg + lane; e < end; e += 32) {
        float4 as = ((const float4*)g_attS)[g_ssrc[e]];
        t0 += __expf(lrelu(as.x + ad.x) - m0);
        t1 += __expf(lrelu(as.y + ad.y) - m1);
        t2 += __expf(lrelu(as.z + ad.z) - m2);
        t3 += __expf(lrelu(as.w + ad.w) - m3);
    }
#pragma unroll
    for (int off = 16; off; off >>= 1) {
        t0 += __shfl_xor_sync(0xffffffffu, t0, off);
        t1 += __shfl_xor_sync(0xffffffffu, t1, off);
        t2 += __shfl_xor_sync(0xffffffffu, t2, off);
        t3 += __shfl_xor_sync(0xffffffffu, t3, off);
    }
    float i0 = 1.f / (t0 + 1e-16f);
    float i1 = 1.f / (t1 + 1e-16f);
    float i2 = 1.f / (t2 + 1e-16f);
    float i3 = 1.f / (t3 + 1e-16f);

    // pass 3: serial over edges; lanes own 8 of 256 channels; head per slot = k>>1
    float acc[8] = {0.f,0.f,0.f,0.f,0.f,0.f,0.f,0.f};
    for (int e = beg; e < end; e++) {
        int s = g_ssrc[e];
        float4 as = ((const float4*)g_attS)[s];
        float a0 = __expf(lrelu(as.x + ad.x) - m0) * i0;
        float a1 = __expf(lrelu(as.y + ad.y) - m1) * i1;
        float a2 = __expf(lrelu(as.z + ad.z) - m2) * i2;
        float a3 = __expf(lrelu(as.w + ad.w) - m3) * i3;
        if (lane == 0)
            ((float4*)alpha_out)[g_seid[e]] = make_float4(a0, a1, a2, a3);
        const float* row = g_xw + (size_t)s*256;
        acc[0] = fmaf(a0, row[lane      ], acc[0]);
        acc[1] = fmaf(a0, row[lane + 32 ], acc[1]);
        acc[2] = fmaf(a1, row[lane + 64 ], acc[2]);
        acc[3] = fmaf(a1, row[lane + 96 ], acc[3]);
        acc[4] = fmaf(a2, row[lane + 128], acc[4]);
        acc[5] = fmaf(a2, row[lane + 160], acc[5]);
        acc[6] = fmaf(a3, row[lane + 192], acc[6]);
        acc[7] = fmaf(a3, row[lane + 224], acc[7]);
    }

    if (MODE == 0) {
#pragma unroll
        for (int k = 0; k < 8; k++) {
            int ch = lane + 32*k;
            out[(size_t)gw*256 + ch] = fmaxf(acc[k] + bias[ch], 0.f);
        }
    } else {
        float v0 = (acc[0] + acc[2] + acc[4] + acc[6]) * 0.25f + bias[lane];
        float v1 = (acc[1] + acc[3] + acc[5] + acc[7]) * 0.25f + bias[lane + 32];
        if (MODE == 1) { v0 = fmaxf(v0, 0.f); v1 = fmaxf(v1, 0.f); }
        out[(size_t)gw*64 + lane]      = v0;
        out[(size_t)gw*64 + lane + 32] = v1;
    }
}

// ---------------- launch ----------------
extern "C" void kernel_launch(void* const* d_in, const int* in_sizes, int n_in,
                              void* d_out, int out_size) {
    const float* x          = (const float*)d_in[0];
    const int*   ei         = (const int*)  d_in[1];   // [2, E] row-major
    const float* gcn_W      = (const float*)d_in[2];
    const float* gcn_b      = (const float*)d_in[3];
    const float* gat1_W     = (const float*)d_in[4];
    const float* gat1_asrc  = (const float*)d_in[5];
    const float* gat1_adst  = (const float*)d_in[6];
    const float* gat1_b     = (const float*)d_in[7];
    const float* gat2_W     = (const float*)d_in[8];
    const float* gat2_asrc  = (const float*)d_in[9];
    const float* gat2_adst  = (const float*)d_in[10];
    const float* gat2_b     = (const float*)d_in[11];
    const float* mean_W     = (const float*)d_in[12];
    const float* mean_asrc  = (const float*)d_in[13];
    const float* mean_adst  = (const float*)d_in[14];
    const float* mean_b     = (const float*)d_in[15];
    const float* std_W      = (const float*)d_in[16];
    const float* std_asrc   = (const float*)d_in[17];
    const float* std_adst   = (const float*)d_in[18];
    const float* std_b      = (const float*)d_in[19];

    float* out = (float*)d_out;
    float* zm  = out;                              // [20000, 64]
    float* zs  = out + (size_t)N_NODES*64;         // [20000, 64]
    float* a1  = out + (size_t)2*N_NODES*64;       // [340000, 4]
    float* a2  = a1 + (size_t)N_ETOT*4;
    float* am  = a2 + (size_t)N_ETOT*4;
    float* as_ = am + (size_t)N_ETOT*4;

    float *h0, *h1, *h2, *xw;
    cudaGetSymbolAddress((void**)&h0, g_h0);
    cudaGetSymbolAddress((void**)&h1, g_h1);
    cudaGetSymbolAddress((void**)&h2, g_h2);
    cudaGetSymbolAddress((void**)&xw, g_xw);

    const int* src = ei;
    const int* dst = ei + N_EDGES;

    // CSR build
    k_init_counts<<<(N_NODES+255)/256, 256>>>();
    k_count<<<(N_EDGES+255)/256, 256>>>(dst);
    k_scan<<<1, 1024>>>();
    k_finalize<<<(N_NODES+255)/256, 256>>>();
    k_scatter<<<(N_ETOT+255)/256, 256>>>(src, dst);

    dim3 gemm_blk(256);
    int mblocks = (N_NODES + 63) / 64;   // 313
    dim3 warp_grid(2500);                // 2500 blocks * 8 warps = 20000 warps

    // GCN: xw = x @ gcn_W ; h0 = relu(agg + b)
    gemm64<<<dim3(1, mblocks), gemm_blk>>>(x, gcn_W, xw, N_NODES, 64, 128);
    k_gcn_agg<<<warp_grid, 256>>>(gcn_b);

    // GAT1 (concat + relu) -> h1
    gemm64<<<dim3(4, mblocks), gemm_blk>>>(h0, gat1_W, xw, N_NODES, 256, 64);
    k_att<<<warp_grid, 256>>>(gat1_asrc, gat1_adst);
    k_gat_agg<0><<<warp_grid, 256>>>(gat1_b, a1, h1);

    // GAT2 (mean + relu) -> h2
    gemm64<<<dim3(4, mblocks), gemm_blk>>>(h1, gat2_W, xw, N_NODES, 256, 256);
    k_att<<<warp_grid, 256>>>(gat2_asrc, gat2_adst);
    k_gat_agg<1><<<warp_grid, 256>>>(gat2_b, a2, h2);

    // mean head (mean, no relu) -> z_mean
    gemm64<<<dim3(4, mblocks), gemm_blk>>>(h2, mean_W, xw, N_NODES, 256, 64);
    k_att<<<warp_grid, 256>>>(mean_asrc, mean_adst);
    k_gat_agg<2><<<warp_grid, 256>>>(mean_b, am, zm);

    // std head (mean, no relu) -> z_log_std
    gemm64<<<dim3(4, mblocks), gemm_blk>>>(h2, std_W, xw, N_NODES, 256, 64);
    k_att<<<warp_grid, 256>>>(std_asrc, std_adst);
    k_gat_agg<2><<<warp_grid, 256>>>(std_b, as_, zs);
}

// round 4
// speedup vs baseline: 1.0426x; 1.0426x over previous
#include <cuda_runtime.h>
#include <cstdint>
#include <cstddef>

#define N_NODES 20000
#define N_EDGES 320000
#define N_ETOT  340000   // edges + self loops

// ---------------- scratch (static device arrays; no allocation) ----------------
__device__ float g_h0[N_NODES*64];
__device__ float g_h1[N_NODES*256];
__device__ float g_h2[N_NODES*64];
__device__ float g_xw[N_NODES*256];
__device__ float g_attS[N_NODES*4];
__device__ float g_attD[N_NODES*4];
__device__ float g_dis[N_NODES];
__device__ int   g_counts[N_NODES];
__device__ int   g_offs[N_NODES+1];
__device__ int   g_cursor[N_NODES];
__device__ int   g_ssrc[N_ETOT];
__device__ int   g_seid[N_ETOT];

// ---------------- CSR build ----------------
__global__ void k_init_counts() {
    int i = blockIdx.x*blockDim.x + threadIdx.x;
    if (i < N_NODES) g_counts[i] = 1;   // self loop
}

__global__ void k_count(const int* __restrict__ dst) {
    int e = blockIdx.x*blockDim.x + threadIdx.x;
    if (e < N_EDGES) atomicAdd(&g_counts[dst[e]], 1);
}

// single-block exclusive scan over 20000 ints (Hillis-Steele per 1024 chunk)
__global__ void k_scan() {
    __shared__ int sh[1024];
    __shared__ int carry;
    int tid = threadIdx.x;
    if (tid == 0) carry = 0;
    __syncthreads();
    for (int base = 0; base < N_NODES; base += 1024) {
        int i = base + tid;
        int v = (i < N_NODES) ? g_counts[i] : 0;
        sh[tid] = v;
        __syncthreads();
        for (int off = 1; off < 1024; off <<= 1) {
            int t = (tid >= off) ? sh[tid-off] : 0;
            __syncthreads();
            sh[tid] += t;
            __syncthreads();
        }
        if (i < N_NODES) g_offs[i] = carry + sh[tid] - v;  // exclusive
        __syncthreads();
        if (tid == 1023) carry += sh[1023];
        __syncthreads();
    }
    if (tid == 0) g_offs[N_NODES] = carry;
}

__global__ void k_finalize() {
    int i = blockIdx.x*blockDim.x + threadIdx.x;
    if (i < N_NODES) {
        g_cursor[i] = g_offs[i];
        int deg = g_offs[i+1] - g_offs[i];          // in-degree incl self loop, >= 1
        g_dis[i] = rsqrtf((float)deg);
    }
}

__global__ void k_scatter(const int* __restrict__ src, const int* __restrict__ dst) {
    int t = blockIdx.x*blockDim.x + threadIdx.x;
    if (t >= N_ETOT) return;
    int s, d;
    if (t < N_EDGES) { s = src[t]; d = dst[t]; }
    else             { s = t - N_EDGES; d = s; }
    int pos = atomicAdd(&g_cursor[d], 1);
    g_ssrc[pos] = s;
    g_seid[pos] = t;  // original edge id (self loops are E..E+N-1, matching reference concat)
}

// ---------------- GEMM: C[M,N] = A[M,K] @ B[K,N] ----------------
// 128x64 block tile, BK=16, 256 threads, 8x4 per-thread tile (~88% fma issue)
// Requires N % 64 == 0, K % 16 == 0.
__global__ void gemm128(const float* __restrict__ A, const float* __restrict__ B,
                        float* __restrict__ C, int M, int N, int K) {
    __shared__ float As[16][132];   // [k][m], padded (+4)
    __shared__ float Bs[16][64];    // [k][n]
    int tid = threadIdx.x;
    int tx = tid & 15;              // 0..15 -> 4 cols each
    int ty = tid >> 4;              // 0..15 -> 8 rows each
    int row0 = blockIdx.y * 128, col0 = blockIdx.x * 64;

    // A staging: thread loads 8 consecutive k of one row (2 float4)
    int a_r = tid >> 1;             // 0..127
    int a_k = (tid & 1) * 8;        // 0 or 8
    // B staging: thread loads 1 float4
    int b_k = tid >> 4;             // 0..15
    int b_n = (tid & 15) * 4;       // 0..60

    float acc[8][4];
#pragma unroll
    for (int i = 0; i < 8; i++)
#pragma unroll
        for (int j = 0; j < 4; j++) acc[i][j] = 0.f;

    int arow = row0 + a_r;
    bool a_ok = (arow < M);
    const float* a_base = A + (size_t)arow * K + a_k;

    for (int k0 = 0; k0 < K; k0 += 16) {
        float4 av0 = make_float4(0.f,0.f,0.f,0.f);
        float4 av1 = make_float4(0.f,0.f,0.f,0.f);
        if (a_ok) {
            av0 = *(const float4*)(a_base + k0);
            av1 = *(const float4*)(a_base + k0 + 4);
        }
        float4 bv = *(const float4*)(B + (size_t)(k0 + b_k) * N + col0 + b_n);
        As[a_k+0][a_r] = av0.x; As[a_k+1][a_r] = av0.y;
        As[a_k+2][a_r] = av0.z; As[a_k+3][a_r] = av0.w;
        As[a_k+4][a_r] = av1.x; As[a_k+5][a_r] = av1.y;
        As[a_k+6][a_r] = av1.z; As[a_k+7][a_r] = av1.w;
        *(float4*)&Bs[b_k][b_n] = bv;
        __syncthreads();
#pragma unroll
        for (int kk = 0; kk < 16; kk++) {
            float4 a0 = *(float4*)&As[kk][ty*8];
            float4 a1 = *(float4*)&As[kk][ty*8 + 4];
            float4 b  = *(float4*)&Bs[kk][tx*4];
            float ar[8] = {a0.x,a0.y,a0.z,a0.w,a1.x,a1.y,a1.z,a1.w};
            float br[4] = {b.x,b.y,b.z,b.w};
#pragma unroll
            for (int i = 0; i < 8; i++)
#pragma unroll
                for (int j = 0; j < 4; j++)
                    acc[i][j] = fmaf(ar[i], br[j], acc[i][j]);
        }
        __syncthreads();
    }
#pragma unroll
    for (int i = 0; i < 8; i++) {
        int r = row0 + ty*8 + i;
        if (r < M) {
            float4 v = make_float4(acc[i][0], acc[i][1], acc[i][2], acc[i][3]);
            *(float4*)(C + (size_t)r*N + col0 + tx*4) = v;
        }
    }
}

// ---------------- GCN aggregate: warp per destination, 64 channels ----------------
__global__ void k_gcn_agg(const float* __restrict__ bias) {
    int gw = (blockIdx.x*blockDim.x + threadIdx.x) >> 5;
    int lane = threadIdx.x & 31;
    if (gw >= N_NODES) return;
    int beg = g_offs[gw], end = g_offs[gw+1];
    float di = g_dis[gw];
    float a0 = 0.f, a1 = 0.f;
    for (int e = beg; e < end; e++) {
        int s = g_ssrc[e];
        float w = g_dis[s] * di;
        const float* row = g_xw + (size_t)s*64;
        a0 = fmaf(w, row[lane],      a0);
        a1 = fmaf(w, row[lane + 32], a1);
    }
    g_h0[(size_t)gw*64 + lane]      = fmaxf(a0 + bias[lane], 0.f);
    g_h0[(size_t)gw*64 + lane + 32] = fmaxf(a1 + bias[lane+32], 0.f);
}

// ---------------- per-node attention terms: als/ald [N,4] ----------------
__global__ void k_att(const float* __restrict__ asrc, const float* __restrict__ adst) {
    int gw = (blockIdx.x*blockDim.x + threadIdx.x) >> 5;
    int lane = threadIdx.x & 31;
    if (gw >= N_NODES) return;
    const float* row = g_xw + (size_t)gw*256;
    float s[4] = {0.f,0.f,0.f,0.f}, d[4] = {0.f,0.f,0.f,0.f};
#pragma unroll
    for (int k = 0; k < 8; k++) {
        int ch = lane + 32*k;
        int h = k >> 1;            // lane-independent head per slot
        int c = ch & 63;
        float v = row[ch];
        s[h] = fmaf(v, __ldg(&asrc[h*64 + c]), s[h]);
        d[h] = fmaf(v, __ldg(&adst[h*64 + c]), d[h]);
    }
#pragma unroll
    for (int off = 16; off; off >>= 1) {
#pragma unroll
        for (int h = 0; h < 4; h++) {
            s[h] += __shfl_xor_sync(0xffffffffu, s[h], off);
            d[h] += __shfl_xor_sync(0xffffffffu, d[h], off);
        }
    }
    if (lane == 0) {
        ((float4*)g_attS)[gw] = make_float4(s[0], s[1], s[2], s[3]);
        ((float4*)g_attD)[gw] = make_float4(d[0], d[1], d[2], d[3]);
    }
}

__device__ __forceinline__ float lrelu(float x) {
    return fmaxf(x, 0.f) + 0.2f * fminf(x, 0.f);
}

// ---------------- GAT aggregate: warp per destination ----------------
// MODE 0: concat (256 out) + bias + relu   (gat1)
// MODE 1: head-mean (64 out) + bias + relu (gat2)
// MODE 2: head-mean (64 out) + bias        (mean/std)
template<int MODE>
__global__ void k_gat_agg(const float* __restrict__ bias,
                          float* __restrict__ alpha_out,
                          float* __restrict__ out) {
    int gw = (blockIdx.x*blockDim.x + threadIdx.x) >> 5;
    int lane = threadIdx.x & 31;
    if (gw >= N_NODES) return;
    int beg = g_offs[gw], end = g_offs[gw+1];
    float4 ad = ((const float4*)g_attD)[gw];

    // pass 1: per-head max over this node's incoming edges
    float m0 = -3.4e38f, m1 = -3.4e38f, m2 = -3.4e38f, m3 = -3.4e38f;
    for (int e = beg + lane; e < end; e += 32) {
        float4 as = ((const float4*)g_attS)[g_ssrc[e]];
        m0 = fmaxf(m0, lrelu(as.x + ad.x));
        m1 = fmaxf(m1, lrelu(as.y + ad.y));
        m2 = fmaxf(m2, lrelu(as.z + ad.z));
        m3 = fmaxf(m3, lrelu(as.w + ad.w));
    }
#pragma unroll
    for (int off = 16; off; off >>= 1) {
        m0 = fmaxf(m0, __shfl_xor_sync(0xffffffffu, m0, off));
        m1 = fmaxf(m1, __shfl_xor_sync(0xffffffffu, m1, off));
        m2 = fmaxf(m2, __shfl_xor_sync(0xffffffffu, m2, off));
        m3 = fmaxf(m3, __shfl_xor_sync(0xffffffffu, m3, off));
    }

    // pass 2: per-head sum of exp
    float t0 = 0.f, t1 = 0.f, t2 = 0.f, t3 = 0.f;
    for (int e = beg + lane; e < end; e += 32) {
        float4 as = ((const float4*)g_attS)[g_ssrc[e]];
        t0 += __expf(lrelu(as.x + ad.x) - m0);
        t1 += __expf(lrelu(as.y + ad.y) - m1);
        t2 += __expf(lrelu(as.z + ad.z) - m2);
        t3 += __expf(lrelu(as.w + ad.w) - m3);
    }
#pragma unroll
    for (int off = 16; off; off >>= 1) {
        t0 += __shfl_xor_sync(0xffffffffu, t0, off);
        t1 += __shfl_xor_sync(0xffffffffu, t1, off);
        t2 += __shfl_xor_sync(0xffffffffu, t2, off);
        t3 += __shfl_xor_sync(0xffffffffu, t3, off);
    }
    float i0 = 1.f / (t0 + 1e-16f);
    float i1 = 1.f / (t1 + 1e-16f);
    float i2 = 1.f / (t2 + 1e-16f);
    float i3 = 1.f / (t3 + 1e-16f);

    // pass 3: serial over edges; lanes own 8 of 256 channels; head per slot = k>>1
    float acc[8] = {0.f,0.f,0.f,0.f,0.f,0.f,0.f,0.f};
    for (int e = beg; e < end; e++) {
        int s = g_ssrc[e];
        float4 as = ((const float4*)g_attS)[s];
        float a0 = __expf(lrelu(as.x + ad.x) - m0) * i0;
        float a1 = __expf(lrelu(as.y + ad.y) - m1) * i1;
        float a2 = __expf(lrelu(as.z + ad.z) - m2) * i2;
        float a3 = __expf(lrelu(as.w + ad.w) - m3) * i3;
        if (lane == 0)
            ((float4*)alpha_out)[g_seid[e]] = make_float4(a0, a1, a2, a3);
        const float* row = g_xw + (size_t)s*256;
        acc[0] = fmaf(a0, row[lane      ], acc[0]);
        acc[1] = fmaf(a0, row[lane + 32 ], acc[1]);
        acc[2] = fmaf(a1, row[lane + 64 ], acc[2]);
        acc[3] = fmaf(a1, row[lane + 96 ], acc[3]);
        acc[4] = fmaf(a2, row[lane + 128], acc[4]);
        acc[5] = fmaf(a2, row[lane + 160], acc[5]);
        acc[6] = fmaf(a3, row[lane + 192], acc[6]);
        acc[7] = fmaf(a3, row[lane + 224], acc[7]);
    }

    if (MODE == 0) {
#pragma unroll
        for (int k = 0; k < 8; k++) {
            int ch = lane + 32*k;
            out[(size_t)gw*256 + ch] = fmaxf(acc[k] + bias[ch], 0.f);
        }
    } else {
        float v0 = (acc[0] + acc[2] + acc[4] + acc[6]) * 0.25f + bias[lane];
        float v1 = (acc[1] + acc[3] + acc[5] + acc[7]) * 0.25f + bias[lane + 32];
        if (MODE == 1) { v0 = fmaxf(v0, 0.f); v1 = fmaxf(v1, 0.f); }
        out[(size_t)gw*64 + lane]      = v0;
        out[(size_t)gw*64 + lane + 32] = v1;
    }
}

// ---------------- launch ----------------
extern "C" void kernel_launch(void* const* d_in, const int* in_sizes, int n_in,
                              void* d_out, int out_size) {
    const float* x          = (const float*)d_in[0];
    const int*   ei         = (const int*)  d_in[1];   // [2, E] row-major
    const float* gcn_W      = (const float*)d_in[2];
    const float* gcn_b      = (const float*)d_in[3];
    const float* gat1_W     = (const float*)d_in[4];
    const float* gat1_asrc  = (const float*)d_in[5];
    const float* gat1_adst  = (const float*)d_in[6];
    const float* gat1_b     = (const float*)d_in[7];
    const float* gat2_W     = (const float*)d_in[8];
    const float* gat2_asrc  = (const float*)d_in[9];
    const float* gat2_adst  = (const float*)d_in[10];
    const float* gat2_b     = (const float*)d_in[11];
    const float* mean_W     = (const float*)d_in[12];
    const float* mean_asrc  = (const float*)d_in[13];
    const float* mean_adst  = (const float*)d_in[14];
    const float* mean_b     = (const float*)d_in[15];
    const float* std_W      = (const float*)d_in[16];
    const float* std_asrc   = (const float*)d_in[17];
    const float* std_adst   = (const float*)d_in[18];
    const float* std_b      = (const float*)d_in[19];

    float* out = (float*)d_out;
    float* zm  = out;                              // [20000, 64]
    float* zs  = out + (size_t)N_NODES*64;         // [20000, 64]
    float* a1  = out + (size_t)2*N_NODES*64;       // [340000, 4]
    float* a2  = a1 + (size_t)N_ETOT*4;
    float* am  = a2 + (size_t)N_ETOT*4;
    float* as_ = am + (size_t)N_ETOT*4;

    float *h0, *h1, *h2, *xw;
    cudaGetSymbolAddress((void**)&h0, g_h0);
    cudaGetSymbolAddress((void**)&h1, g_h1);
    cudaGetSymbolAddress((void**)&h2, g_h2);
    cudaGetSymbolAddress((void**)&xw, g_xw);

    const int* src = ei;
    const int* dst = ei + N_EDGES;

    // CSR build
    k_init_counts<<<(N_NODES+255)/256, 256>>>();
    k_count<<<(N_EDGES+255)/256, 256>>>(dst);
    k_scan<<<1, 1024>>>();
    k_finalize<<<(N_NODES+255)/256, 256>>>();
    k_scatter<<<(N_ETOT+255)/256, 256>>>(src, dst);

    dim3 gemm_blk(256);
    int mblocks = (N_NODES + 127) / 128;   // 157
    dim3 warp_grid(2500);                  // 2500 blocks * 8 warps = 20000 warps

    // GCN: xw = x @ gcn_W ; h0 = relu(agg + b)
    gemm128<<<dim3(1, mblocks), gemm_blk>>>(x, gcn_W, xw, N_NODES, 64, 128);
    k_gcn_agg<<<warp_grid, 256>>>(gcn_b);

    // GAT1 (concat + relu) -> h1
    gemm128<<<dim3(4, mblocks), gemm_blk>>>(h0, gat1_W, xw, N_NODES, 256, 64);
    k_att<<<warp_grid, 256>>>(gat1_asrc, gat1_adst);
    k_gat_agg<0><<<warp_grid, 256>>>(gat1_b, a1, h1);

    // GAT2 (mean + relu) -> h2
    gemm128<<<dim3(4, mblocks), gemm_blk>>>(h1, gat2_W, xw, N_NODES, 256, 256);
    k_att<<<warp_grid, 256>>>(gat2_asrc, gat2_adst);
    k_gat_agg<1><<<warp_grid, 256>>>(gat2_b, a2, h2);

    // mean head (mean, no relu) -> z_mean
    gemm128<<<dim3(4, mblocks), gemm_blk>>>(h2, mean_W, xw, N_NODES, 256, 64);
    k_att<<<warp_grid, 256>>>(mean_asrc, mean_adst);
    k_gat_agg<2><<<warp_grid, 256>>>(mean_b, am, zm);

    // std head (mean, no relu) -> z_log_std
    gemm128<<<dim3(4, mblocks), gemm_blk>>>(h2, std_W, xw, N_NODES, 256, 64);
    k_att<<<warp_grid, 256>>>(std_asrc, std_adst);
    k_gat_agg<2><<<warp_grid, 256>>>(std_b, as_, zs);
}

// round 6
// speedup vs baseline: 1.3306x; 1.2762x over previous
#include <cuda_runtime.h>
#include <cstdint>
#include <cstddef>

#define N_NODES 20000
#define N_EDGES 320000
#define N_ETOT  340000   // edges + self loops

// ---------------- scratch (static device arrays; no allocation) ----------------
__device__ float g_h0[N_NODES*64];
__device__ float g_h1[N_NODES*256];
__device__ float g_h2[N_NODES*64];
__device__ float g_xw0[N_NODES*256];
__device__ float g_xw1[N_NODES*256];
__device__ float g_attS0[N_NODES*4];
__device__ float g_attD0[N_NODES*4];
__device__ float g_attS1[N_NODES*4];
__device__ float g_attD1[N_NODES*4];
__device__ float g_dis[N_NODES];
__device__ int   g_counts[N_NODES];
__device__ int   g_offs[N_NODES+1];
__device__ int   g_cursor[N_NODES];
__device__ int   g_ssrc[N_ETOT];
__device__ int   g_seid[N_ETOT];
__device__ float4 g_elog0[N_ETOT];
__device__ float4 g_elog1[N_ETOT];

// ---------------- CSR build ----------------
__global__ void k_init_counts() {
    int i = blockIdx.x*blockDim.x + threadIdx.x;
    if (i < N_NODES) g_counts[i] = 1;   // self loop
}

__global__ void k_count(const int* __restrict__ dst) {
    int e = blockIdx.x*blockDim.x + threadIdx.x;
    if (e < N_EDGES) atomicAdd(&g_counts[dst[e]], 1);
}

// single-block exclusive scan: 1024 threads x 20 elems, 2 barriers total
__global__ void k_scan() {
    __shared__ int wsum[32];
    const int PER = 20;
    int tid = threadIdx.x;
    int lane = tid & 31, w = tid >> 5;
    int base = tid * PER;
    int loc[PER];
    int s = 0;
#pragma unroll
    for (int i = 0; i < PER; i++) {
        int idx = base + i;
        int v = (idx < N_NODES) ? g_counts[idx] : 0;
        loc[i] = s;                 // exclusive within thread
        s += v;
    }
    // warp inclusive scan of s
    int incl = s;
#pragma unroll
    for (int off = 1; off < 32; off <<= 1) {
        int t = __shfl_up_sync(0xffffffffu, incl, off);
        if (lane >= off) incl += t;
    }
    if (lane == 31) wsum[w] = incl;
    __syncthreads();
    if (w == 0) {
        int v = wsum[lane];
        int inc2 = v;
#pragma unroll
        for (int off = 1; off < 32; off <<= 1) {
            int t = __shfl_up_sync(0xffffffffu, inc2, off);
            if (lane >= off) inc2 += t;
        }
        wsum[lane] = inc2 - v;     // exclusive warp base
    }
    __syncthreads();
    int excl = incl - s + wsum[w];
#pragma unroll
    for (int i = 0; i < PER; i++) {
        int idx = base + i;
        if (idx < N_NODES) g_offs[idx] = excl + loc[i];
    }
    if (tid == 1023) g_offs[N_NODES] = excl + s;
}

__global__ void k_finalize() {
    int i = blockIdx.x*blockDim.x + threadIdx.x;
    if (i < N_NODES) {
        g_cursor[i] = g_offs[i];
        int deg = g_offs[i+1] - g_offs[i];          // in-degree incl self loop, >= 1
        g_dis[i] = rsqrtf((float)deg);
    }
}

__global__ void k_scatter(const int* __restrict__ src, const int* __restrict__ dst) {
    int t = blockIdx.x*blockDim.x + threadIdx.x;
    if (t >= N_ETOT) return;
    int s, d;
    if (t < N_EDGES) { s = src[t]; d = dst[t]; }
    else             { s = t - N_EDGES; d = s; }
    int pos = atomicAdd(&g_cursor[d], 1);
    g_ssrc[pos] = s;
    g_seid[pos] = t;  // original edge id (self loops are E..E+N-1, matching reference concat)
}

// ---------------- GEMM: C[M,N] = A[M,K] @ B[K,N] ----------------
// 128x64 block tile, BK=16, 256 threads, 8x4 per-thread tile.
// blockIdx.z selects (B0,C0) or (B1,C1).  N%64==0, K%16==0.
__global__ void gemm128(const float* __restrict__ A,
                        const float* __restrict__ B0, const float* __restrict__ B1,
                        float* __restrict__ C0, float* __restrict__ C1,
                        int M, int N, int K) {
    const float* B = blockIdx.z ? B1 : B0;
    float*       C = blockIdx.z ? C1 : C0;
    __shared__ float As[16][132];   // [k][m], padded (+4)
    __shared__ float Bs[16][64];    // [k][n]
    int tid = threadIdx.x;
    int tx = tid & 15;              // 0..15 -> 4 cols each
    int ty = tid >> 4;              // 0..15 -> 8 rows each
    int row0 = blockIdx.y * 128, col0 = blockIdx.x * 64;

    int a_r = tid >> 1;             // 0..127
    int a_k = (tid & 1) * 8;        // 0 or 8
    int b_k = tid >> 4;             // 0..15
    int b_n = (tid & 15) * 4;       // 0..60

    float acc[8][4];
#pragma unroll
    for (int i = 0; i < 8; i++)
#pragma unroll
        for (int j = 0; j < 4; j++) acc[i][j] = 0.f;

    int arow = row0 + a_r;
    bool a_ok = (arow < M);
    const float* a_base = A + (size_t)arow * K + a_k;

    for (int k0 = 0; k0 < K; k0 += 16) {
        float4 av0 = make_float4(0.f,0.f,0.f,0.f);
        float4 av1 = make_float4(0.f,0.f,0.f,0.f);
        if (a_ok) {
            av0 = *(const float4*)(a_base + k0);
            av1 = *(const float4*)(a_base + k0 + 4);
        }
        float4 bv = *(const float4*)(B + (size_t)(k0 + b_k) * N + col0 + b_n);
        As[a_k+0][a_r] = av0.x; As[a_k+1][a_r] = av0.y;
        As[a_k+2][a_r] = av0.z; As[a_k+3][a_r] = av0.w;
        As[a_k+4][a_r] = av1.x; As[a_k+5][a_r] = av1.y;
        As[a_k+6][a_r] = av1.z; As[a_k+7][a_r] = av1.w;
        *(float4*)&Bs[b_k][b_n] = bv;
        __syncthreads();
#pragma unroll
        for (int kk = 0; kk < 16; kk++) {
            float4 a0 = *(float4*)&As[kk][ty*8];
            float4 a1 = *(float4*)&As[kk][ty*8 + 4];
            float4 b  = *(float4*)&Bs[kk][tx*4];
            float ar[8] = {a0.x,a0.y,a0.z,a0.w,a1.x,a1.y,a1.z,a1.w};
            float br[4] = {b.x,b.y,b.z,b.w};
#pragma unroll
            for (int i = 0; i < 8; i++)
#pragma unroll
                for (int j = 0; j < 4; j++)
                    acc[i][j] = fmaf(ar[i], br[j], acc[i][j]);
        }
        __syncthreads();
    }
#pragma unroll
    for (int i = 0; i < 8; i++) {
        int r = row0 + ty*8 + i;
        if (r < M) {
            float4 v = make_float4(acc[i][0], acc[i][1], acc[i][2], acc[i][3]);
            *(float4*)(C + (size_t)r*N + col0 + tx*4) = v;
        }
    }
}

// ---------------- GCN aggregate: warp per destination, 64 channels ----------------
__global__ void k_gcn_agg(const float* __restrict__ bias) {
    int gw = (blockIdx.x*blockDim.x + threadIdx.x) >> 5;
    int lane = threadIdx.x & 31;
    if (gw >= N_NODES) return;
    int beg = g_offs[gw], end = g_offs[gw+1];
    float di = g_dis[gw];
    float a0 = 0.f, a1 = 0.f;
#pragma unroll 2
    for (int e = beg; e < end; e++) {
        int s = g_ssrc[e];
        float w = g_dis[s] * di;
        const float* row = g_xw0 + (size_t)s*64;
        a0 = fmaf(w, row[lane],      a0);
        a1 = fmaf(w, row[lane + 32], a1);
    }
    g_h0[(size_t)gw*64 + lane]      = fmaxf(a0 + bias[lane], 0.f);
    g_h0[(size_t)gw*64 + lane + 32] = fmaxf(a1 + bias[lane+32], 0.f);
}

// ---------------- per-node attention terms: als/ald [N,4]; z selects set ----------------
__global__ void k_att(const float* __restrict__ asrc0, const float* __restrict__ adst0,
                      const float* __restrict__ asrc1, const float* __restrict__ adst1) {
    const float* asrc = blockIdx.z ? asrc1 : asrc0;
    const float* adst = blockIdx.z ? adst1 : adst0;
    const float* xw   = blockIdx.z ? g_xw1 : g_xw0;
    float* attS = blockIdx.z ? g_attS1 : g_attS0;
    float* attD = blockIdx.z ? g_attD1 : g_attD0;
    int gw = (blockIdx.x*blockDim.x + threadIdx.x) >> 5;
    int lane = threadIdx.x & 31;
    if (gw >= N_NODES) return;
    const float* row = xw + (size_t)gw*256;
    float s[4] = {0.f,0.f,0.f,0.f}, d[4] = {0.f,0.f,0.f,0.f};
#pragma unroll
    for (int k = 0; k < 8; k++) {
        int ch = lane + 32*k;
        int h = k >> 1;            // lane-independent head per slot
        int c = ch & 63;
        float v = row[ch];
        s[h] = fmaf(v, __ldg(&asrc[h*64 + c]), s[h]);
        d[h] = fmaf(v, __ldg(&adst[h*64 + c]), d[h]);
    }
#pragma unroll
    for (int off = 16; off; off >>= 1) {
#pragma unroll
        for (int h = 0; h < 4; h++) {
            s[h] += __shfl_xor_sync(0xffffffffu, s[h], off);
            d[h] += __shfl_xor_sync(0xffffffffu, d[h], off);
        }
    }
    if (lane == 0) {
        ((float4*)attS)[gw] = make_float4(s[0], s[1], s[2], s[3]);
        ((float4*)attD)[gw] = make_float4(d[0], d[1], d[2], d[3]);
    }
}

__device__ __forceinline__ float lrelu(float x) {
    return fmaxf(x, 0.f) + 0.2f * fminf(x, 0.f);
}

// ---------------- GAT aggregate: warp per destination; z selects branch ----------------
// MODE 0: concat (256 out) + bias + relu   (gat1)
// MODE 1: head-mean (64 out) + bias + relu (gat2)
// MODE 2: head-mean (64 out) + bias        (mean/std, z=0/1)
template<int MODE>
__global__ void k_gat_agg(const float* __restrict__ bias0, const float* __restrict__ bias1,
                          float* __restrict__ aout0, float* __restrict__ aout1,
                          float* __restrict__ out0,  float* __restrict__ out1) {
    const float* bias  = blockIdx.z ? bias1 : bias0;
    float* alpha_out   = blockIdx.z ? aout1 : aout0;
    float* out         = blockIdx.z ? out1  : out0;
    const float* xw    = blockIdx.z ? g_xw1 : g_xw0;
    const float4* attS = blockIdx.z ? (const float4*)g_attS1 : (const float4*)g_attS0;
    const float4* attD = blockIdx.z ? (const float4*)g_attD1 : (const float4*)g_attD0;
    float4* elog       = blockIdx.z ? g_elog1 : g_elog0;

    int gw = (blockIdx.x*blockDim.x + threadIdx.x) >> 5;
    int lane = threadIdx.x & 31;
    if (gw >= N_NODES) return;
    int beg = g_offs[gw], end = g_offs[gw+1];
    float4 ad = attD[gw];

    // sweep A (parallel): logits -> elog, track per-head max
    float m0 = -3.4e38f, m1 = -3.4e38f, m2 = -3.4e38f, m3 = -3.4e38f;
    for (int e = beg + lane; e < end; e += 32) {
        float4 as = attS[g_ssrc[e]];
        float4 l = make_float4(lrelu(as.x + ad.x), lrelu(as.y + ad.y),
                               lrelu(as.z + ad.z), lrelu(as.w + ad.w));
        elog[e] = l;
        m0 = fmaxf(m0, l.x); m1 = fmaxf(m1, l.y);
        m2 = fmaxf(m2, l.z); m3 = fmaxf(m3, l.w);
    }
#pragma unroll
    for (int off = 16; off; off >>= 1) {
        m0 = fmaxf(m0, __shfl_xor_sync(0xffffffffu, m0, off));
        m1 = fmaxf(m1, __shfl_xor_sync(0xffffffffu, m1, off));
        m2 = fmaxf(m2, __shfl_xor_sync(0xffffffffu, m2, off));
        m3 = fmaxf(m3, __shfl_xor_sync(0xffffffffu, m3, off));
    }

    // sweep B (parallel): exp in place, sum
    float t0 = 0.f, t1 = 0.f, t2 = 0.f, t3 = 0.f;
    for (int e = beg + lane; e < end; e += 32) {
        float4 l = elog[e];
        float4 p = make_float4(__expf(l.x - m0), __expf(l.y - m1),
                               __expf(l.z - m2), __expf(l.w - m3));
        elog[e] = p;
        t0 += p.x; t1 += p.y; t2 += p.z; t3 += p.w;
    }
#pragma unroll
    for (int off = 16; off; off >>= 1) {
        t0 += __shfl_xor_sync(0xffffffffu, t0, off);
        t1 += __shfl_xor_sync(0xffffffffu, t1, off);
        t2 += __shfl_xor_sync(0xffffffffu, t2, off);
        t3 += __shfl_xor_sync(0xffffffffu, t3, off);
    }
    float i0 = 1.f / (t0 + 1e-16f);
    float i1 = 1.f / (t1 + 1e-16f);
    float i2 = 1.f / (t2 + 1e-16f);
    float i3 = 1.f / (t3 + 1e-16f);

    // sweep C (parallel): write normalized alpha to original edge ids
    for (int e = beg + lane; e < end; e += 32) {
        float4 p = elog[e];
        ((float4*)alpha_out)[g_seid[e]] =
            make_float4(p.x*i0, p.y*i1, p.z*i2, p.w*i3);
    }

    // sweep D (serial over edges): contiguous elog reads + row gathers only
    float acc[8] = {0.f,0.f,0.f,0.f,0.f,0.f,0.f,0.f};
#pragma unroll 2
    for (int e = beg; e < end; e++) {
        int s = g_ssrc[e];
        float4 p = elog[e];
        float a0 = p.x * i0, a1 = p.y * i1, a2 = p.z * i2, a3 = p.w * i3;
        const float* row = xw + (size_t)s*256;
        acc[0] = fmaf(a0, row[lane      ], acc[0]);
        acc[1] = fmaf(a0, row[lane + 32 ], acc[1]);
        acc[2] = fmaf(a1, row[lane + 64 ], acc[2]);
        acc[3] = fmaf(a1, row[lane + 96 ], acc[3]);
        acc[4] = fmaf(a2, row[lane + 128], acc[4]);
        acc[5] = fmaf(a2, row[lane + 160], acc[5]);
        acc[6] = fmaf(a3, row[lane + 192], acc[6]);
        acc[7] = fmaf(a3, row[lane + 224], acc[7]);
    }

    if (MODE == 0) {
#pragma unroll
        for (int k = 0; k < 8; k++) {
            int ch = lane + 32*k;
            out[(size_t)gw*256 + ch] = fmaxf(acc[k] + bias[ch], 0.f);
        }
    } else {
        float v0 = (acc[0] + acc[2] + acc[4] + acc[6]) * 0.25f + bias[lane];
        float v1 = (acc[1] + acc[3] + acc[5] + acc[7]) * 0.25f + bias[lane + 32];
        if (MODE == 1) { v0 = fmaxf(v0, 0.f); v1 = fmaxf(v1, 0.f); }
        out[(size_t)gw*64 + lane]      = v0;
        out[(size_t)gw*64 + lane + 32] = v1;
    }
}

// ---------------- launch ----------------
extern "C" void kernel_launch(void* const* d_in, const int* in_sizes, int n_in,
                              void* d_out, int out_size) {
    const float* x          = (const float*)d_in[0];
    const int*   ei         = (const int*)  d_in[1];   // [2, E] row-major
    const float* gcn_W      = (const float*)d_in[2];
    const float* gcn_b      = (const float*)d_in[3];
    const float* gat1_W     = (const float*)d_in[4];
    const float* gat1_asrc  = (const float*)d_in[5];
    const float* gat1_adst  = (const float*)d_in[6];
    const float* gat1_b     = (const float*)d_in[7];
    const float* gat2_W     = (const float*)d_in[8];
    const float* gat2_asrc  = (const float*)d_in[9];
    const float* gat2_adst  = (const float*)d_in[10];
    const float* gat2_b     = (const float*)d_in[11];
    const float* mean_W     = (const float*)d_in[12];
    const float* mean_asrc  = (const float*)d_in[13];
    const float* mean_adst  = (const float*)d_in[14];
    const float* mean_b     = (const float*)d_in[15];
    const float* std_W      = (const float*)d_in[16];
    const float* std_asrc   = (const float*)d_in[17];
    const float* std_adst   = (const float*)d_in[18];
    const float* std_b      = (const float*)d_in[19];

    float* out = (float*)d_out;
    float* zm  = out;                              // [20000, 64]
    float* zs  = out + (size_t)N_NODES*64;         // [20000, 64]
    float* a1  = out + (size_t)2*N_NODES*64;       // [340000, 4]
    float* a2  = a1 + (size_t)N_ETOT*4;
    float* am  = a2 + (size_t)N_ETOT*4;
    float* as_ = am + (size_t)N_ETOT*4;

    float *h0, *h1, *h2, *xw0, *xw1;
    cudaGetSymbolAddress((void**)&h0, g_h0);
    cudaGetSymbolAddress((void**)&h1, g_h1);
    cudaGetSymbolAddress((void**)&h2, g_h2);
    cudaGetSymbolAddress((void**)&xw0, g_xw0);
    cudaGetSymbolAddress((void**)&xw1, g_xw1);

    const int* src = ei;
    const int* dst = ei + N_EDGES;

    // CSR build
    k_init_counts<<<(N_NODES+255)/256, 256>>>();
    k_count<<<(N_EDGES+255)/256, 256>>>(dst);
    k_scan<<<1, 1024>>>();
    k_finalize<<<(N_NODES+255)/256, 256>>>();
    k_scatter<<<(N_ETOT+255)/256, 256>>>(src, dst);

    dim3 gemm_blk(256);
    int mblocks = (N_NODES + 127) / 128;   // 157
    dim3 warp_grid(2500);                  // 2500 blocks * 8 warps = 20000 warps
    dim3 warp_grid2(2500, 1, 2);

    // GCN: xw0 = x @ gcn_W ; h0 = relu(agg + b)
    gemm128<<<dim3(1, mblocks, 1), gemm_blk>>>(x, gcn_W, gcn_W, xw0, xw0, N_NODES, 64, 128);
    k_gcn_agg<<<warp_grid, 256>>>(gcn_b);

    // GAT1 (concat + relu) -> h1
    gemm128<<<dim3(4, mblocks, 1), gemm_blk>>>(h0, gat1_W, gat1_W, xw0, xw0, N_NODES, 256, 64);
    k_att<<<warp_grid, 256>>>(gat1_asrc, gat1_adst, gat1_asrc, gat1_adst);
    k_gat_agg<0><<<warp_grid, 256>>>(gat1_b, gat1_b, a1, a1, h1, h1);

    // GAT2 (mean + relu) -> h2
    gemm128<<<dim3(4, mblocks, 1), gemm_blk>>>(h1, gat2_W, gat2_W, xw0, xw0, N_NODES, 256, 256);
    k_att<<<warp_grid, 256>>>(gat2_asrc, gat2_adst, gat2_asrc, gat2_adst);
    k_gat_agg<1><<<warp_grid, 256>>>(gat2_b, gat2_b, a2, a2, h2, h2);

    // mean + std branches merged via gridDim.z = 2
    gemm128<<<dim3(4, mblocks, 2), gemm_blk>>>(h2, mean_W, std_W, xw0, xw1, N_NODES, 256, 64);
    k_att<<<warp_grid2, 256>>>(mean_asrc, mean_adst, std_asrc, std_adst);
    k_gat_agg<2><<<warp_grid2, 256>>>(mean_b, std_b, am, as_, zm, zs);
}

// round 9
// speedup vs baseline: 1.3328x; 1.0016x over previous
#include <cuda_runtime.h>
#include <cstdint>
#include <cstddef>

#define N_NODES 20000
#define N_EDGES 320000
#define N_ETOT  340000   // edges + self loops

// ---------------- scratch (static device arrays; no allocation) ----------------
__device__ float g_h0[N_NODES*64];
__device__ float g_h1[N_NODES*256];
__device__ float g_h2[N_NODES*64];
__device__ float g_xw0[N_NODES*256];
__device__ float g_xw1[N_NODES*256];
__device__ float g_attS0[N_NODES*4];
__device__ float g_attD0[N_NODES*4];
__device__ float g_attS1[N_NODES*4];
__device__ float g_attD1[N_NODES*4];
__device__ float g_dis[N_NODES];
__device__ int   g_counts[N_NODES];
__device__ int   g_offs[N_NODES+1];
__device__ int   g_cursor[N_NODES];
__device__ int   g_ssrc[N_ETOT];
__device__ int   g_seid[N_ETOT];
__device__ float4 g_elog0[N_ETOT];
__device__ float4 g_elog1[N_ETOT];

// ---------------- CSR build ----------------
__global__ void k_init_counts() {
    int i = blockIdx.x*blockDim.x + threadIdx.x;
    if (i < N_NODES) g_counts[i] = 1;   // self loop
}

__global__ void k_count(const int* __restrict__ dst) {
    int e = blockIdx.x*blockDim.x + threadIdx.x;
    if (e < N_EDGES) atomicAdd(&g_counts[dst[e]], 1);
}

// single-block exclusive scan: 1024 threads x 20 elems, 2 barriers total
__global__ void k_scan() {
    __shared__ int wsum[32];
    const int PER = 20;
    int tid = threadIdx.x;
    int lane = tid & 31, w = tid >> 5;
    int base = tid * PER;
    int loc[PER];
    int s = 0;
#pragma unroll
    for (int i = 0; i < PER; i++) {
        int idx = base + i;
        int v = (idx < N_NODES) ? g_counts[idx] : 0;
        loc[i] = s;                 // exclusive within thread
        s += v;
    }
    // warp inclusive scan of s
    int incl = s;
#pragma unroll
    for (int off = 1; off < 32; off <<= 1) {
        int t = __shfl_up_sync(0xffffffffu, incl, off);
        if (lane >= off) incl += t;
    }
    if (lane == 31) wsum[w] = incl;
    __syncthreads();
    if (w == 0) {
        int v = wsum[lane];
        int inc2 = v;
#pragma unroll
        for (int off = 1; off < 32; off <<= 1) {
            int t = __shfl_up_sync(0xffffffffu, inc2, off);
            if (lane >= off) inc2 += t;
        }
        wsum[lane] = inc2 - v;     // exclusive warp base
    }
    __syncthreads();
    int excl = incl - s + wsum[w];
#pragma unroll
    for (int i = 0; i < PER; i++) {
        int idx = base + i;
        if (idx < N_NODES) g_offs[idx] = excl + loc[i];
    }
    if (tid == 1023) g_offs[N_NODES] = excl + s;
}

__global__ void k_finalize() {
    int i = blockIdx.x*blockDim.x + threadIdx.x;
    if (i < N_NODES) {
        g_cursor[i] = g_offs[i];
        int deg = g_offs[i+1] - g_offs[i];          // in-degree incl self loop, >= 1
        g_dis[i] = rsqrtf((float)deg);
    }
}

__global__ void k_scatter(const int* __restrict__ src, const int* __restrict__ dst) {
    int t = blockIdx.x*blockDim.x + threadIdx.x;
    if (t >= N_ETOT) return;
    int s, d;
    if (t < N_EDGES) { s = src[t]; d = dst[t]; }
    else             { s = t - N_EDGES; d = s; }
    int pos = atomicAdd(&g_cursor[d], 1);
    g_ssrc[pos] = s;
    g_seid[pos] = t;  // original edge id (self loops are E..E+N-1, matching reference concat)
}

// ---------------- GEMM: C[M,N] = A[M,K] @ B[K,N] ----------------
// 128x64 block tile, BK=16, 256 threads, 8x4 per-thread tile.
// blockIdx.z selects (B0,C0) or (B1,C1).  N%64==0, K%16==0.
__global__ void gemm128(const float* __restrict__ A,
                        const float* __restrict__ B0, const float* __restrict__ B1,
                        float* __restrict__ C0, float* __restrict__ C1,
                        int M, int N, int K) {
    const float* B = blockIdx.z ? B1 : B0;
    float*       C = blockIdx.z ? C1 : C0;
    __shared__ float As[16][132];   // [k][m], padded (+4)
    __shared__ float Bs[16][64];    // [k][n]
    int tid = threadIdx.x;
    int tx = tid & 15;              // 0..15 -> 4 cols each
    int ty = tid >> 4;              // 0..15 -> 8 rows each
    int row0 = blockIdx.y * 128, col0 = blockIdx.x * 64;

    int a_r = tid >> 1;             // 0..127
    int a_k = (tid & 1) * 8;        // 0 or 8
    int b_k = tid >> 4;             // 0..15
    int b_n = (tid & 15) * 4;       // 0..60

    float acc[8][4];
#pragma unroll
    for (int i = 0; i < 8; i++)
#pragma unroll
        for (int j = 0; j < 4; j++) acc[i][j] = 0.f;

    int arow = row0 + a_r;
    bool a_ok = (arow < M);
    const float* a_base = A + (size_t)arow * K + a_k;

    for (int k0 = 0; k0 < K; k0 += 16) {
        float4 av0 = make_float4(0.f,0.f,0.f,0.f);
        float4 av1 = make_float4(0.f,0.f,0.f,0.f);
        if (a_ok) {
            av0 = *(const float4*)(a_base + k0);
            av1 = *(const float4*)(a_base + k0 + 4);
        }
        float4 bv = *(const float4*)(B + (size_t)(k0 + b_k) * N + col0 + b_n);
        As[a_k+0][a_r] = av0.x; As[a_k+1][a_r] = av0.y;
        As[a_k+2][a_r] = av0.z; As[a_k+3][a_r] = av0.w;
        As[a_k+4][a_r] = av1.x; As[a_k+5][a_r] = av1.y;
        As[a_k+6][a_r] = av1.z; As[a_k+7][a_r] = av1.w;
        *(float4*)&Bs[b_k][b_n] = bv;
        __syncthreads();
#pragma unroll
        for (int kk = 0; kk < 16; kk++) {
            float4 a0 = *(float4*)&As[kk][ty*8];
            float4 a1 = *(float4*)&As[kk][ty*8 + 4];
            float4 b  = *(float4*)&Bs[kk][tx*4];
            float ar[8] = {a0.x,a0.y,a0.z,a0.w,a1.x,a1.y,a1.z,a1.w};
            float br[4] = {b.x,b.y,b.z,b.w};
#pragma unroll
            for (int i = 0; i < 8; i++)
#pragma unroll
                for (int j = 0; j < 4; j++)
                    acc[i][j] = fmaf(ar[i], br[j], acc[i][j]);
        }
        __syncthreads();
    }
#pragma unroll
    for (int i = 0; i < 8; i++) {
        int r = row0 + ty*8 + i;
        if (r < M) {
            float4 v = make_float4(acc[i][0], acc[i][1], acc[i][2], acc[i][3]);
            *(float4*)(C + (size_t)r*N + col0 + tx*4) = v;
        }
    }
}

// ---------------- GCN aggregate: warp per destination, 64 channels ----------------
__global__ void k_gcn_agg(const float* __restrict__ bias) {
    int gw = (blockIdx.x*blockDim.x + threadIdx.x) >> 5;
    int lane = threadIdx.x & 31;
    if (gw >= N_NODES) return;
    int beg = g_offs[gw], end = g_offs[gw+1];
    float di = g_dis[gw];
    float a0 = 0.f, a1 = 0.f;
#pragma unroll 2
    for (int e = beg; e < end; e++) {
        int s = g_ssrc[e];
        float w = g_dis[s] * di;
        const float* row = g_xw0 + (size_t)s*64;
        a0 = fmaf(w, row[lane],      a0);
        a1 = fmaf(w, row[lane + 32], a1);
    }
    g_h0[(size_t)gw*64 + lane]      = fmaxf(a0 + bias[lane], 0.f);
    g_h0[(size_t)gw*64 + lane + 32] = fmaxf(a1 + bias[lane+32], 0.f);
}

// ---------------- per-node attention terms: als/ald [N,4]; z selects set ----------------
__global__ void k_att(const float* __restrict__ asrc0, const float* __restrict__ adst0,
                      const float* __restrict__ asrc1, const float* __restrict__ adst1) {
    const float* asrc = blockIdx.z ? asrc1 : asrc0;
    const float* adst = blockIdx.z ? adst1 : adst0;
    const float* xw   = blockIdx.z ? g_xw1 : g_xw0;
    float* attS = blockIdx.z ? g_attS1 : g_attS0;
    float* attD = blockIdx.z ? g_attD1 : g_attD0;
    int gw = (blockIdx.x*blockDim.x + threadIdx.x) >> 5;
    int lane = threadIdx.x & 31;
    if (gw >= N_NODES) return;
    const float* row = xw + (size_t)gw*256;
    float s[4] = {0.f,0.f,0.f,0.f}, d[4] = {0.f,0.f,0.f,0.f};
#pragma unroll
    for (int k = 0; k < 8; k++) {
        int ch = lane + 32*k;
        int h = k >> 1;            // lane-independent head per slot
        int c = ch & 63;
        float v = row[ch];
        s[h] = fmaf(v, __ldg(&asrc[h*64 + c]), s[h]);
        d[h] = fmaf(v, __ldg(&adst[h*64 + c]), d[h]);
    }
#pragma unroll
    for (int off = 16; off; off >>= 1) {
#pragma unroll
        for (int h = 0; h < 4; h++) {
            s[h] += __shfl_xor_sync(0xffffffffu, s[h], off);
            d[h] += __shfl_xor_sync(0xffffffffu, d[h], off);
        }
    }
    if (lane == 0) {
        ((float4*)attS)[gw] = make_float4(s[0], s[1], s[2], s[3]);
        ((float4*)attD)[gw] = make_float4(d[0], d[1], d[2], d[3]);
    }
}

__device__ __forceinline__ float lrelu(float x) {
    return fmaxf(x, 0.f) + 0.2f * fminf(x, 0.f);
}

// ---------------- GAT aggregate: warp per destination; z selects branch ----------------
// MODE 0: concat (256 out) + bias + relu   (gat1)
// MODE 1: head-mean (64 out) + bias + relu (gat2)
// MODE 2: head-mean (64 out) + bias        (mean/std, z=0/1)
template<int MODE>
__global__ void k_gat_agg(const float* __restrict__ bias0, const float* __restrict__ bias1,
                          float* __restrict__ aout0, float* __restrict__ aout1,
                          float* __restrict__ out0,  float* __restrict__ out1) {
    const float* bias  = blockIdx.z ? bias1 : bias0;
    float* alpha_out   = blockIdx.z ? aout1 : aout0;
    float* out         = blockIdx.z ? out1  : out0;
    const float* xw    = blockIdx.z ? g_xw1 : g_xw0;
    const float4* attS = blockIdx.z ? (const float4*)g_attS1 : (const float4*)g_attS0;
    const float4* attD = blockIdx.z ? (const float4*)g_attD1 : (const float4*)g_attD0;
    float4* elog       = blockIdx.z ? g_elog1 : g_elog0;

    int gw = (blockIdx.x*blockDim.x + threadIdx.x) >> 5;
    int lane = threadIdx.x & 31;
    if (gw >= N_NODES) return;
    int beg = g_offs[gw], end = g_offs[gw+1];
    float4 ad = attD[gw];

    // sweep A (parallel): logits -> elog, track per-head max
    float m0 = -3.4e38f, m1 = -3.4e38f, m2 = -3.4e38f, m3 = -3.4e38f;
    for (int e = beg + lane; e < end; e += 32) {
        float4 as = attS[g_ssrc[e]];
        float4 l = make_float4(lrelu(as.x + ad.x), lrelu(as.y + ad.y),
                               lrelu(as.z + ad.z), lrelu(as.w + ad.w));
        elog[e] = l;
        m0 = fmaxf(m0, l.x); m1 = fmaxf(m1, l.y);
        m2 = fmaxf(m2, l.z); m3 = fmaxf(m3, l.w);
    }
#pragma unroll
    for (int off = 16; off; off >>= 1) {
        m0 = fmaxf(m0, __shfl_xor_sync(0xffffffffu, m0, off));
        m1 = fmaxf(m1, __shfl_xor_sync(0xffffffffu, m1, off));
        m2 = fmaxf(m2, __shfl_xor_sync(0xffffffffu, m2, off));
        m3 = fmaxf(m3, __shfl_xor_sync(0xffffffffu, m3, off));
    }

    // sweep B (parallel): exp in place, sum
    float t0 = 0.f, t1 = 0.f, t2 = 0.f, t3 = 0.f;
    for (int e = beg + lane; e < end; e += 32) {
        float4 l = elog[e];
        float4 p = make_float4(__expf(l.x - m0), __expf(l.y - m1),
                               __expf(l.z - m2), __expf(l.w - m3));
        elog[e] = p;
        t0 += p.x; t1 += p.y; t2 += p.z; t3 += p.w;
    }
#pragma unroll
    for (int off = 16; off; off >>= 1) {
        t0 += __shfl_xor_sync(0xffffffffu, t0, off);
        t1 += __shfl_xor_sync(0xffffffffu, t1, off);
        t2 += __shfl_xor_sync(0xffffffffu, t2, off);
        t3 += __shfl_xor_sync(0xffffffffu, t3, off);
    }
    float i0 = 1.f / (t0 + 1e-16f);
    float i1 = 1.f / (t1 + 1e-16f);
    float i2 = 1.f / (t2 + 1e-16f);
    float i3 = 1.f / (t3 + 1e-16f);

    // sweep C (parallel): write normalized alpha to original edge ids
    for (int e = beg + lane; e < end; e += 32) {
        float4 p = elog[e];
        ((float4*)alpha_out)[g_seid[e]] =
            make_float4(p.x*i0, p.y*i1, p.z*i2, p.w*i3);
    }

    // sweep D (serial over edges): contiguous elog reads + row gathers only
    float acc[8] = {0.f,0.f,0.f,0.f,0.f,0.f,0.f,0.f};
#pragma unroll 2
    for (int e = beg; e < end; e++) {
        int s = g_ssrc[e];
        float4 p = elog[e];
        float a0 = p.x * i0, a1 = p.y * i1, a2 = p.z * i2, a3 = p.w * i3;
        const float* row = xw + (size_t)s*256;
        acc[0] = fmaf(a0, row[lane      ], acc[0]);
        acc[1] = fmaf(a0, row[lane + 32 ], acc[1]);
        acc[2] = fmaf(a1, row[lane + 64 ], acc[2]);
        acc[3] = fmaf(a1, row[lane + 96 ], acc[3]);
        acc[4] = fmaf(a2, row[lane + 128], acc[4]);
        acc[5] = fmaf(a2, row[lane + 160], acc[5]);
        acc[6] = fmaf(a3, row[lane + 192], acc[6]);
        acc[7] = fmaf(a3, row[lane + 224], acc[7]);
    }

    if (MODE == 0) {
#pragma unroll
        for (int k = 0; k < 8; k++) {
            int ch = lane + 32*k;
            out[(size_t)gw*256 + ch] = fmaxf(acc[k] + bias[ch], 0.f);
        }
    } else {
        float v0 = (acc[0] + acc[2] + acc[4] + acc[6]) * 0.25f + bias[lane];
        float v1 = (acc[1] + acc[3] + acc[5] + acc[7]) * 0.25f + bias[lane + 32];
        if (MODE == 1) { v0 = fmaxf(v0, 0.f); v1 = fmaxf(v1, 0.f); }
        out[(size_t)gw*64 + lane]      = v0;
        out[(size_t)gw*64 + lane + 32] = v1;
    }
}

// ---------------- launch ----------------
extern "C" void kernel_launch(void* const* d_in, const int* in_sizes, int n_in,
                              void* d_out, int out_size) {
    const float* x          = (const float*)d_in[0];
    const int*   ei         = (const int*)  d_in[1];   // [2, E] row-major
    const float* gcn_W      = (const float*)d_in[2];
    const float* gcn_b      = (const float*)d_in[3];
    const float* gat1_W     = (const float*)d_in[4];
    const float* gat1_asrc  = (const float*)d_in[5];
    const float* gat1_adst  = (const float*)d_in[6];
    const float* gat1_b     = (const float*)d_in[7];
    const float* gat2_W     = (const float*)d_in[8];
    const float* gat2_asrc  = (const float*)d_in[9];
    const float* gat2_adst  = (const float*)d_in[10];
    const float* gat2_b     = (const float*)d_in[11];
    const float* mean_W     = (const float*)d_in[12];
    const float* mean_asrc  = (const float*)d_in[13];
    const float* mean_adst  = (const float*)d_in[14];
    const float* mean_b     = (const float*)d_in[15];
    const float* std_W      = (const float*)d_in[16];
    const float* std_asrc   = (const float*)d_in[17];
    const float* std_adst   = (const float*)d_in[18];
    const float* std_b      = (const float*)d_in[19];

    float* out = (float*)d_out;
    float* zm  = out;                              // [20000, 64]
    float* zs  = out + (size_t)N_NODES*64;         // [20000, 64]
    float* a1  = out + (size_t)2*N_NODES*64;       // [340000, 4]
    float* a2  = a1 + (size_t)N_ETOT*4;
    float* am  = a2 + (size_t)N_ETOT*4;
    float* as_ = am + (size_t)N_ETOT*4;

    float *h0, *h1, *h2, *xw0, *xw1;
    cudaGetSymbolAddress((void**)&h0, g_h0);
    cudaGetSymbolAddress((void**)&h1, g_h1);
    cudaGetSymbolAddress((void**)&h2, g_h2);
    cudaGetSymbolAddress((void**)&xw0, g_xw0);
    cudaGetSymbolAddress((void**)&xw1, g_xw1);

    const int* src = ei;
    const int* dst = ei + N_EDGES;

    // CSR build
    k_init_counts<<<(N_NODES+255)/256, 256>>>();
    k_count<<<(N_EDGES+255)/256, 256>>>(dst);
    k_scan<<<1, 1024>>>();
    k_finalize<<<(N_NODES+255)/256, 256>>>();
    k_scatter<<<(N_ETOT+255)/256, 256>>>(src, dst);

    dim3 gemm_blk(256);
    int mblocks = (N_NODES + 127) / 128;   // 157
    dim3 warp_grid(2500);                  // 2500 blocks * 8 warps = 20000 warps
    dim3 warp_grid2(2500, 1, 2);

    // GCN: xw0 = x @ gcn_W ; h0 = relu(agg + b)
    gemm128<<<dim3(1, mblocks, 1), gemm_blk>>>(x, gcn_W, gcn_W, xw0, xw0, N_NODES, 64, 128);
    k_gcn_agg<<<warp_grid, 256>>>(gcn_b);

    // GAT1 (concat + relu) -> h1
    gemm128<<<dim3(4, mblocks, 1), gemm_blk>>>(h0, gat1_W, gat1_W, xw0, xw0, N_NODES, 256, 64);
    k_att<<<warp_grid, 256>>>(gat1_asrc, gat1_adst, gat1_asrc, gat1_adst);
    k_gat_agg<0><<<warp_grid, 256>>>(gat1_b, gat1_b, a1, a1, h1, h1);

    // GAT2 (mean + relu) -> h2
    gemm128<<<dim3(4, mblocks, 1), gemm_blk>>>(h1, gat2_W, gat2_W, xw0, xw0, N_NODES, 256, 256);
    k_att<<<warp_grid, 256>>>(gat2_asrc, gat2_adst, gat2_asrc, gat2_adst);
    k_gat_agg<1><<<warp_grid, 256>>>(gat2_b, gat2_b, a2, a2, h2, h2);

    // mean + std branches merged via gridDim.z = 2
    gemm128<<<dim3(4, mblocks, 2), gemm_blk>>>(h2, mean_W, std_W, xw0, xw1, N_NODES, 256, 64);
    k_att<<<warp_grid2, 256>>>(mean_asrc, mean_adst, std_asrc, std_adst);
    k_gat_agg<2><<<warp_grid2, 256>>>(mean_b, std_b, am, as_, zm, zs);
}

// round 10
// speedup vs baseline: 1.6284x; 1.2218x over previous
#include <cuda_runtime.h>
#include <cstdint>
#include <cstddef>

#define N_NODES 20000
#define N_EDGES 320000
#define N_ETOT  340000   // edges + self loops

// ---------------- scratch (static device arrays; no allocation) ----------------
__device__ float g_h0[N_NODES*64];
__device__ float g_h1[N_NODES*256];
__device__ float g_h2[N_NODES*64];
__device__ float g_xw0[N_NODES*256];
__device__ float g_xw1[N_NODES*256];
__device__ float g_attS0[N_NODES*4];
__device__ float g_attD0[N_NODES*4];
__device__ float g_attS1[N_NODES*4];
__device__ float g_attD1[N_NODES*4];
__device__ float g_dis[N_NODES];
__device__ int   g_counts[N_NODES];
__device__ int   g_offs[N_NODES+1];
__device__ int   g_cursor[N_NODES];
__device__ int   g_ssrc[N_ETOT];
__device__ int   g_seid[N_ETOT];
__device__ float4 g_elog0[N_ETOT];
__device__ float4 g_elog1[N_ETOT];

// ---------------- CSR build ----------------
__global__ void k_init_counts() {
    int i = blockIdx.x*blockDim.x + threadIdx.x;
    if (i < N_NODES) g_counts[i] = 1;   // self loop
}

__global__ void k_count(const int* __restrict__ dst) {
    int e = blockIdx.x*blockDim.x + threadIdx.x;
    if (e < N_EDGES) atomicAdd(&g_counts[dst[e]], 1);
}

// single-block exclusive scan: 1024 threads x 20 elems, 2 barriers total
__global__ void k_scan() {
    __shared__ int wsum[32];
    const int PER = 20;
    int tid = threadIdx.x;
    int lane = tid & 31, w = tid >> 5;
    int base = tid * PER;
    int loc[PER];
    int s = 0;
#pragma unroll
    for (int i = 0; i < PER; i++) {
        int idx = base + i;
        int v = (idx < N_NODES) ? g_counts[idx] : 0;
        loc[i] = s;                 // exclusive within thread
        s += v;
    }
    int incl = s;
#pragma unroll
    for (int off = 1; off < 32; off <<= 1) {
        int t = __shfl_up_sync(0xffffffffu, incl, off);
        if (lane >= off) incl += t;
    }
    if (lane == 31) wsum[w] = incl;
    __syncthreads();
    if (w == 0) {
        int v = wsum[lane];
        int inc2 = v;
#pragma unroll
        for (int off = 1; off < 32; off <<= 1) {
            int t = __shfl_up_sync(0xffffffffu, inc2, off);
            if (lane >= off) inc2 += t;
        }
        wsum[lane] = inc2 - v;     // exclusive warp base
    }
    __syncthreads();
    int excl = incl - s + wsum[w];
#pragma unroll
    for (int i = 0; i < PER; i++) {
        int idx = base + i;
        if (idx < N_NODES) g_offs[idx] = excl + loc[i];
    }
    if (tid == 1023) g_offs[N_NODES] = excl + s;
}

__global__ void k_finalize() {
    int i = blockIdx.x*blockDim.x + threadIdx.x;
    if (i < N_NODES) {
        g_cursor[i] = g_offs[i];
        int deg = g_offs[i+1] - g_offs[i];          // in-degree incl self loop, >= 1
        g_dis[i] = rsqrtf((float)deg);
    }
}

__global__ void k_scatter(const int* __restrict__ src, const int* __restrict__ dst) {
    int t = blockIdx.x*blockDim.x + threadIdx.x;
    if (t >= N_ETOT) return;
    int s, d;
    if (t < N_EDGES) { s = src[t]; d = dst[t]; }
    else             { s = t - N_EDGES; d = s; }
    int pos = atomicAdd(&g_cursor[d], 1);
    g_ssrc[pos] = s;
    g_seid[pos] = t;  // original edge id (self loops are E..E+N-1, matching reference concat)
}

// ---------------- tf32 tensor-core GEMM: C[M,N] = A[M,K] @ B[K,N] ----------------
// 128x64 block tile, BK=32, 256 threads = 8 warps (4m x 2n), 32x32 warp tile.
// mma.sync.m16n8k8 tf32, cvt.rna rounding at staging.
// Requires N % 64 == 0, K % 32 == 0.  blockIdx.z selects (B0,C0)/(B1,C1).
__device__ __forceinline__ float to_tf32(float x) {
    float y;
    asm("cvt.rna.tf32.f32 %0, %1;" : "=f"(y) : "f"(x));
    return y;
}

__global__ void gemm_tc(const float* __restrict__ A,
                        const float* __restrict__ B0, const float* __restrict__ B1,
                        float* __restrict__ C0, float* __restrict__ C1,
                        int M, int N, int K) {
    const float* B = blockIdx.z ? B1 : B0;
    float*       C = blockIdx.z ? C1 : C0;
    __shared__ float As[128][36];   // [m][k], stride 36 -> frag banks = lane (conflict-free)
    __shared__ float Bs[32][72];    // [k][n], stride 72 -> frag banks = lane (conflict-free)

    int tid = threadIdx.x;
    int lane = tid & 31, wid = tid >> 5;
    int wm = wid & 3, wn = wid >> 2;          // warp tile: rows 32*wm, cols 32*wn
    int t4 = lane >> 2, c4 = lane & 3;
    int row0 = blockIdx.y * 128, col0 = blockIdx.x * 64;

    // A staging: thread -> row tid>>1, 16 k's starting at (tid&1)*16
    int a_r = tid >> 1;
    int a_kb = (tid & 1) * 16;
    int arow = row0 + a_r;
    bool a_ok = (arow < M);
    // B staging: thread -> k = tid>>3, 8 n's at (tid&7)*8
    int b_k = tid >> 3;
    int b_n = (tid & 7) * 8;

    float acc[2][4][4];
#pragma unroll
    for (int mt = 0; mt < 2; mt++)
#pragma unroll
        for (int nt = 0; nt < 4; nt++)
#pragma unroll
            for (int i = 0; i < 4; i++) acc[mt][nt][i] = 0.f;

    for (int k0 = 0; k0 < K; k0 += 32) {
        // stage A (with tf32 rounding)
#pragma unroll
        for (int q = 0; q < 4; q++) {
            int kk = a_kb + q*4;
            float4 v = make_float4(0.f,0.f,0.f,0.f);
            if (a_ok) v = *(const float4*)(A + (size_t)arow*K + k0 + kk);
            v.x = to_tf32(v.x); v.y = to_tf32(v.y);
            v.z = to_tf32(v.z); v.w = to_tf32(v.w);
            *(float4*)&As[a_r][kk] = v;
        }
        // stage B
#pragma unroll
        for (int q = 0; q < 2; q++) {
            float4 v = *(const float4*)(B + (size_t)(k0 + b_k)*N + col0 + b_n + q*4);
            v.x = to_tf32(v.x); v.y = to_tf32(v.y);
            v.z = to_tf32(v.z); v.w = to_tf32(v.w);
            *(float4*)&Bs[b_k][b_n + q*4] = v;
        }
        __syncthreads();

#pragma unroll
        for (int ks = 0; ks < 32; ks += 8) {
            // A fragments: 2 m-tiles
            uint32_t af[2][4];
#pragma unroll
            for (int mt = 0; mt < 2; mt++) {
                int r = wm*32 + mt*16 + t4;
                af[mt][0] = __float_as_uint(As[r    ][ks + c4    ]);
                af[mt][1] = __float_as_uint(As[r + 8][ks + c4    ]);
                af[mt][2] = __float_as_uint(As[r    ][ks + c4 + 4]);
                af[mt][3] = __float_as_uint(As[r + 8][ks + c4 + 4]);
            }
            // B fragments: 4 n-tiles
            uint32_t bf[4][2];
#pragma unroll
            for (int nt = 0; nt < 4; nt++) {
                int n = wn*32 + nt*8 + t4;
                bf[nt][0] = __float_as_uint(Bs[ks + c4    ][n]);
                bf[nt][1] = __float_as_uint(Bs[ks + c4 + 4][n]);
            }
#pragma unroll
            for (int mt = 0; mt < 2; mt++)
#pragma unroll
                for (int nt = 0; nt < 4; nt++) {
                    asm volatile(
                        "mma.sync.aligned.m16n8k8.row.col.f32.tf32.tf32.f32 "
                        "{%0,%1,%2,%3}, {%4,%5,%6,%7}, {%8,%9}, {%0,%1,%2,%3};"
                        : "+f"(acc[mt][nt][0]), "+f"(acc[mt][nt][1]),
                          "+f"(acc[mt][nt][2]), "+f"(acc[mt][nt][3])
                        : "r"(af[mt][0]), "r"(af[mt][1]), "r"(af[mt][2]), "r"(af[mt][3]),
                          "r"(bf[nt][0]), "r"(bf[nt][1]));
                }
        }
        __syncthreads();
    }

    // epilogue: c0,c1 -> (r, c..c+1); c2,c3 -> (r+8, c..c+1)
#pragma unroll
    for (int mt = 0; mt < 2; mt++) {
        int r = row0 + wm*32 + mt*16 + t4;
#pragma unroll
        for (int nt = 0; nt < 4; nt++) {
            int c = col0 + wn*32 + nt*8 + c4*2;
            if (r < M)
                *(float2*)(C + (size_t)r*N + c) = make_float2(acc[mt][nt][0], acc[mt][nt][1]);
            if (r + 8 < M)
                *(float2*)(C + (size_t)(r+8)*N + c) = make_float2(acc[mt][nt][2], acc[mt][nt][3]);
        }
    }
}

// ---------------- GCN aggregate: warp per destination, 64 channels ----------------
__global__ void k_gcn_agg(const float* __restrict__ bias) {
    int gw = (blockIdx.x*blockDim.x + threadIdx.x) >> 5;
    int lane = threadIdx.x & 31;
    if (gw >= N_NODES) return;
    int beg = g_offs[gw], end = g_offs[gw+1];
    float di = g_dis[gw];
    float a0 = 0.f, a1 = 0.f;
#pragma unroll 2
    for (int e = beg; e < end; e++) {
        int s = g_ssrc[e];
        float w = g_dis[s] * di;
        const float* row = g_xw0 + (size_t)s*64;
        a0 = fmaf(w, row[lane],      a0);
        a1 = fmaf(w, row[lane + 32], a1);
    }
    g_h0[(size_t)gw*64 + lane]      = fmaxf(a0 + bias[lane], 0.f);
    g_h0[(size_t)gw*64 + lane + 32] = fmaxf(a1 + bias[lane+32], 0.f);
}

// ---------------- per-node attention terms: als/ald [N,4]; z selects set ----------------
__global__ void k_att(const float* __restrict__ asrc0, const float* __restrict__ adst0,
                      const float* __restrict__ asrc1, const float* __restrict__ adst1) {
    const float* asrc = blockIdx.z ? asrc1 : asrc0;
    const float* adst = blockIdx.z ? adst1 : adst0;
    const float* xw   = blockIdx.z ? g_xw1 : g_xw0;
    float* attS = blockIdx.z ? g_attS1 : g_attS0;
    float* attD = blockIdx.z ? g_attD1 : g_attD0;
    int gw = (blockIdx.x*blockDim.x + threadIdx.x) >> 5;
    int lane = threadIdx.x & 31;
    if (gw >= N_NODES) return;
    const float* row = xw + (size_t)gw*256;
    float s[4] = {0.f,0.f,0.f,0.f}, d[4] = {0.f,0.f,0.f,0.f};
#pragma unroll
    for (int k = 0; k < 8; k++) {
        int ch = lane + 32*k;
        int h = k >> 1;            // lane-independent head per slot
        int c = ch & 63;
        float v = row[ch];
        s[h] = fmaf(v, __ldg(&asrc[h*64 + c]), s[h]);
        d[h] = fmaf(v, __ldg(&adst[h*64 + c]), d[h]);
    }
#pragma unroll
    for (int off = 16; off; off >>= 1) {
#pragma unroll
        for (int h = 0; h < 4; h++) {
            s[h] += __shfl_xor_sync(0xffffffffu, s[h], off);
            d[h] += __shfl_xor_sync(0xffffffffu, d[h], off);
        }
    }
    if (lane == 0) {
        ((float4*)attS)[gw] = make_float4(s[0], s[1], s[2], s[3]);
        ((float4*)attD)[gw] = make_float4(d[0], d[1], d[2], d[3]);
    }
}

__device__ __forceinline__ float lrelu(float x) {
    return fmaxf(x, 0.f) + 0.2f * fminf(x, 0.f);
}

// ---------------- GAT aggregate: warp per destination; z selects branch ----------------
// MODE 0: concat (256 out) + bias + relu   (gat1)
// MODE 1: head-mean (64 out) + bias + relu (gat2)
// MODE 2: head-mean (64 out) + bias        (mean/std, z=0/1)
template<int MODE>
__global__ void k_gat_agg(const float* __restrict__ bias0, const float* __restrict__ bias1,
                          float* __restrict__ aout0, float* __restrict__ aout1,
                          float* __restrict__ out0,  float* __restrict__ out1) {
    const float* bias  = blockIdx.z ? bias1 : bias0;
    float* alpha_out   = blockIdx.z ? aout1 : aout0;
    float* out         = blockIdx.z ? out1  : out0;
    const float* xw    = blockIdx.z ? g_xw1 : g_xw0;
    const float4* attS = blockIdx.z ? (const float4*)g_attS1 : (const float4*)g_attS0;
    const float4* attD = blockIdx.z ? (const float4*)g_attD1 : (const float4*)g_attD0;
    float4* elog       = blockIdx.z ? g_elog1 : g_elog0;

    int gw = (blockIdx.x*blockDim.x + threadIdx.x) >> 5;
    int lane = threadIdx.x & 31;
    if (gw >= N_NODES) return;
    int beg = g_offs[gw], end = g_offs[gw+1];
    float4 ad = attD[gw];

    // sweep A (parallel): logits -> elog, track per-head max
    float m0 = -3.4e38f, m1 = -3.4e38f, m2 = -3.4e38f, m3 = -3.4e38f;
    for (int e = beg + lane; e < end; e += 32) {
        float4 as = attS[g_ssrc[e]];
        float4 l = make_float4(lrelu(as.x + ad.x), lrelu(as.y + ad.y),
                               lrelu(as.z + ad.z), lrelu(as.w + ad.w));
        elog[e] = l;
        m0 = fmaxf(m0, l.x); m1 = fmaxf(m1, l.y);
        m2 = fmaxf(m2, l.z); m3 = fmaxf(m3, l.w);
    }
#pragma unroll
    for (int off = 16; off; off >>= 1) {
        m0 = fmaxf(m0, __shfl_xor_sync(0xffffffffu, m0, off));
        m1 = fmaxf(m1, __shfl_xor_sync(0xffffffffu, m1, off));
        m2 = fmaxf(m2, __shfl_xor_sync(0xffffffffu, m2, off));
        m3 = fmaxf(m3, __shfl_xor_sync(0xffffffffu, m3, off));
    }

    // sweep B (parallel): exp in place, sum
    float t0 = 0.f, t1 = 0.f, t2 = 0.f, t3 = 0.f;
    for (int e = beg + lane; e < end; e += 32) {
        float4 l = elog[e];
        float4 p = make_float4(__expf(l.x - m0), __expf(l.y - m1),
                               __expf(l.z - m2), __expf(l.w - m3));
        elog[e] = p;
        t0 += p.x; t1 += p.y; t2 += p.z; t3 += p.w;
    }
#pragma unroll
    for (int off = 16; off; off >>= 1) {
        t0 += __shfl_xor_sync(0xffffffffu, t0, off);
        t1 += __shfl_xor_sync(0xffffffffu, t1, off);
        t2 += __shfl_xor_sync(0xffffffffu, t2, off);
        t3 += __shfl_xor_sync(0xffffffffu, t3, off);
    }
    float i0 = 1.f / (t0 + 1e-16f);
    float i1 = 1.f / (t1 + 1e-16f);
    float i2 = 1.f / (t2 + 1e-16f);
    float i3 = 1.f / (t3 + 1e-16f);

    // sweep C (parallel): write normalized alpha to original edge ids
    for (int e = beg + lane; e < end; e += 32) {
        float4 p = elog[e];
        ((float4*)alpha_out)[g_seid[e]] =
            make_float4(p.x*i0, p.y*i1, p.z*i2, p.w*i3);
    }

    // sweep D (serial over edges): contiguous elog reads + row gathers only
    float acc[8] = {0.f,0.f,0.f,0.f,0.f,0.f,0.f,0.f};
#pragma unroll 2
    for (int e = beg; e < end; e++) {
        int s = g_ssrc[e];
        float4 p = elog[e];
        float a0 = p.x * i0, a1 = p.y * i1, a2 = p.z * i2, a3 = p.w * i3;
        const float* row = xw + (size_t)s*256;
        acc[0] = fmaf(a0, row[lane      ], acc[0]);
        acc[1] = fmaf(a0, row[lane + 32 ], acc[1]);
        acc[2] = fmaf(a1, row[lane + 64 ], acc[2]);
        acc[3] = fmaf(a1, row[lane + 96 ], acc[3]);
        acc[4] = fmaf(a2, row[lane + 128], acc[4]);
        acc[5] = fmaf(a2, row[lane + 160], acc[5]);
        acc[6] = fmaf(a3, row[lane + 192], acc[6]);
        acc[7] = fmaf(a3, row[lane + 224], acc[7]);
    }

    if (MODE == 0) {
#pragma unroll
        for (int k = 0; k < 8; k++) {
            int ch = lane + 32*k;
            out[(size_t)gw*256 + ch] = fmaxf(acc[k] + bias[ch], 0.f);
        }
    } else {
        float v0 = (acc[0] + acc[2] + acc[4] + acc[6]) * 0.25f + bias[lane];
        float v1 = (acc[1] + acc[3] + acc[5] + acc[7]) * 0.25f + bias[lane + 32];
        if (MODE == 1) { v0 = fmaxf(v0, 0.f); v1 = fmaxf(v1, 0.f); }
        out[(size_t)gw*64 + lane]      = v0;
        out[(size_t)gw*64 + lane + 32] = v1;
    }
}

// ---------------- launch ----------------
extern "C" void kernel_launch(void* const* d_in, const int* in_sizes, int n_in,
                              void* d_out, int out_size) {
    const float* x          = (const float*)d_in[0];
    const int*   ei         = (const int*)  d_in[1];   // [2, E] row-major
    const float* gcn_W      = (const float*)d_in[2];
    const float* gcn_b      = (const float*)d_in[3];
    const float* gat1_W     = (const float*)d_in[4];
    const float* gat1_asrc  = (const float*)d_in[5];
    const float* gat1_adst  = (const float*)d_in[6];
    const float* gat1_b     = (const float*)d_in[7];
    const float* gat2_W     = (const float*)d_in[8];
    const float* gat2_asrc  = (const float*)d_in[9];
    const float* gat2_adst  = (const float*)d_in[10];
    const float* gat2_b     = (const float*)d_in[11];
    const float* mean_W     = (const float*)d_in[12];
    const float* mean_asrc  = (const float*)d_in[13];
    const float* mean_adst  = (const float*)d_in[14];
    const float* mean_b     = (const float*)d_in[15];
    const float* std_W      = (const float*)d_in[16];
    const float* std_asrc   = (const float*)d_in[17];
    const float* std_adst   = (const float*)d_in[18];
    const float* std_b      = (const float*)d_in[19];

    float* out = (float*)d_out;
    float* zm  = out;                              // [20000, 64]
    float* zs  = out + (size_t)N_NODES*64;         // [20000, 64]
    float* a1  = out + (size_t)2*N_NODES*64;       // [340000, 4]
    float* a2  = a1 + (size_t)N_ETOT*4;
    float* am  = a2 + (size_t)N_ETOT*4;
    float* as_ = am + (size_t)N_ETOT*4;

    float *h0, *h1, *h2, *xw0, *xw1;
    cudaGetSymbolAddress((void**)&h0, g_h0);
    cudaGetSymbolAddress((void**)&h1, g_h1);
    cudaGetSymbolAddress((void**)&h2, g_h2);
    cudaGetSymbolAddress((void**)&xw0, g_xw0);
    cudaGetSymbolAddress((void**)&xw1, g_xw1);

    const int* src = ei;
    const int* dst = ei + N_EDGES;

    // CSR build
    k_init_counts<<<(N_NODES+255)/256, 256>>>();
    k_count<<<(N_EDGES+255)/256, 256>>>(dst);
    k_scan<<<1, 1024>>>();
    k_finalize<<<(N_NODES+255)/256, 256>>>();
    k_scatter<<<(N_ETOT+255)/256, 256>>>(src, dst);

    dim3 gemm_blk(256);
    int mblocks = (N_NODES + 127) / 128;   // 157
    dim3 warp_grid(2500);                  // 2500 blocks * 8 warps = 20000 warps
    dim3 warp_grid2(2500, 1, 2);

    // GCN: xw0 = x @ gcn_W ; h0 = relu(agg + b)
    gemm_tc<<<dim3(1, mblocks, 1), gemm_blk>>>(x, gcn_W, gcn_W, xw0, xw0, N_NODES, 64, 128);
    k_gcn_agg<<<warp_grid, 256>>>(gcn_b);

    // GAT1 (concat + relu) -> h1
    gemm_tc<<<dim3(4, mblocks, 1), gemm_blk>>>(h0, gat1_W, gat1_W, xw0, xw0, N_NODES, 256, 64);
    k_att<<<warp_grid, 256>>>(gat1_asrc, gat1_adst, gat1_asrc, gat1_adst);
    k_gat_agg<0><<<warp_grid, 256>>>(gat1_b, gat1_b, a1, a1, h1, h1);

    // GAT2 (mean + relu) -> h2
    gemm_tc<<<dim3(4, mblocks, 1), gemm_blk>>>(h1, gat2_W, gat2_W, xw0, xw0, N_NODES, 256, 256);
    k_att<<<warp_grid, 256>>>(gat2_asrc, gat2_adst, gat2_asrc, gat2_adst);
    k_gat_agg<1><<<warp_grid, 256>>>(gat2_b, gat2_b, a2, a2, h2, h2);

    // mean + std branches merged via gridDim.z = 2
    gemm_tc<<<dim3(4, mblocks, 2), gemm_blk>>>(h2, mean_W, std_W, xw0, xw1, N_NODES, 256, 64);
    k_att<<<warp_grid2, 256>>>(mean_asrc, mean_adst, std_asrc, std_adst);
    k_gat_agg<2><<<warp_grid2, 256>>>(mean_b, std_b, am, as_, zm, zs);
}